// round 11
// baseline (speedup 1.0000x reference)
#include <cuda_runtime.h>
#include <cuda_fp16.h>
#include <math.h>
#include <stdint.h>

// ----------------------------------------------------------------------------
// Causal masked softmax attention. N=64, T=1024, D=64.
// Warp-specialized pipeline: 8 compute warps (BM=128 queries) + 4 loader
// warps; K/V double-buffered in 128-key stages; named-barrier full/empty
// handshake (bar.arrive / bar.sync, 384 threads per use).
// All-fp16 tensor GEMMs (fp16 mantissa == tf32 mantissa), fp32 accum/softmax.
//   QK^T: m16n8k16, A=Q regs (ldmatrix.x4 once), B=K via ldmatrix.x4.
//   PV:   m16n8k16, A=P regs (C-layout == A-layout), B=V via ldmatrix.x4.trans.
// Key-padding mask: additive bias (0/-1e30) from a 16-lane ballot on raw K.
// ----------------------------------------------------------------------------

namespace {
constexpr int kT = 1024;
constexpr int BM = 128;
constexpr int BK2 = 128;       // keys per pipeline stage
constexpr int kD = 64;
constexpr int NCON = 256;      // consumer threads (8 warps)
constexpr int NPRO = 128;      // producer threads (4 warps)
constexpr int THREADS = NCON + NPRO;
constexpr int STRH = 72;       // row stride in halves (144 B)
constexpr float kQScale = 0.18033688011112042f;  // (1/8) * log2(e)
constexpr float kPad = -1e30f;
// smem words: buffer p at p*BUFW { K 128x36 | V 128x36 }, then bias[2][128]
constexpr int BUFW = BK2 * (STRH / 2) * 2;       // 9216 words per buffer
constexpr int VOFF_W = BK2 * (STRH / 2);         // 4608 words: V within buffer
constexpr int SB_W = 2 * BUFW;                   // 18432
constexpr int SMEM_WORDS = SB_W + 2 * BK2;       // 18688 words = 73 KB
// named barrier ids: full[p] = 1+p, empty[p] = 3+p
}  // namespace

__device__ __forceinline__ float ex2f(float x) {
    float r; asm("ex2.approx.ftz.f32 %0, %1;" : "=f"(r) : "f"(x)); return r;
}
__device__ __forceinline__ uint32_t f2h2(float lo, float hi) {
    __half2 h = __floats2half2_rn(lo, hi);
    return *reinterpret_cast<uint32_t*>(&h);
}
__device__ __forceinline__ void bar_sync(int id) {
    asm volatile("bar.sync %0, %1;" :: "r"(id), "n"(THREADS) : "memory");
}
__device__ __forceinline__ void bar_arrive(int id) {
    asm volatile("bar.arrive %0, %1;" :: "r"(id), "n"(THREADS) : "memory");
}
__device__ __forceinline__ void mma_f16(float (&d)[4],
                                        uint32_t a0, uint32_t a1,
                                        uint32_t a2, uint32_t a3,
                                        uint32_t b0, uint32_t b1) {
    asm volatile(
        "mma.sync.aligned.m16n8k16.row.col.f32.f16.f16.f32 "
        "{%0,%1,%2,%3}, {%4,%5,%6,%7}, {%8,%9}, {%0,%1,%2,%3};\n"
        : "+f"(d[0]), "+f"(d[1]), "+f"(d[2]), "+f"(d[3])
        : "r"(a0), "r"(a1), "r"(a2), "r"(a3), "r"(b0), "r"(b1));
}
__device__ __forceinline__ void ldsm_x4(uint32_t& r0, uint32_t& r1,
                                        uint32_t& r2, uint32_t& r3,
                                        uint32_t addr) {
    asm volatile(
        "ldmatrix.sync.aligned.m8n8.x4.shared.b16 {%0,%1,%2,%3}, [%4];\n"
        : "=r"(r0), "=r"(r1), "=r"(r2), "=r"(r3) : "r"(addr));
}
__device__ __forceinline__ void ldsm_x4_trans(uint32_t& r0, uint32_t& r1,
                                              uint32_t& r2, uint32_t& r3,
                                              uint32_t addr) {
    asm volatile(
        "ldmatrix.sync.aligned.m8n8.x4.trans.shared.b16 {%0,%1,%2,%3}, [%4];\n"
        : "=r"(r0), "=r"(r1), "=r"(r2), "=r"(r3) : "r"(addr));
}

__global__ __launch_bounds__(THREADS, 1)
void attn_ws_kernel(const float* __restrict__ Q, const float* __restrict__ K,
                    const float* __restrict__ V, float* __restrict__ O) {
    extern __shared__ float sm[];
    uint32_t* sH2 = (uint32_t*)sm;             // buffers (half2 view)

    const int tid = threadIdx.x;
    const int warp = tid >> 5;   // 0..11
    const int lane = tid & 31;
    const int qt = (kT / BM - 1) - blockIdx.x;   // heavy q-tiles first
    const int bn = blockIdx.y;
    const int q0 = qt * BM;

    const float* Qg = Q + ((size_t)bn * kT + q0) * kD;
    const float* Kg = K + (size_t)bn * kT * kD;
    const float* Vg = V + (size_t)bn * kT * kD;

    const uint32_t base = (uint32_t)__cvta_generic_to_shared(sm);  // bytes
    const int nrounds = qt + 1;

    // ---- stage Q (scaled fp16) into buf0 K region; consumed before pipeline -
    if (tid < NCON) {
        const int tx = tid & 15, ty = tid >> 4;  // 16x16
#pragma unroll
        for (int i = 0; i < 8; i++) {
            const int r = ty + 16 * i;           // 0..127
            float4 qv = *(const float4*)(Qg + (size_t)r * kD + 4 * tx);
            *(uint2*)(sH2 + r * (STRH / 2) + 2 * tx) =
                make_uint2(f2h2(qv.x * kQScale, qv.y * kQScale),
                           f2h2(qv.z * kQScale, qv.w * kQScale));
        }
    }
    __syncthreads();
    uint32_t qf[4][4];
    if (warp < 8) {
        const uint32_t qrow = warp * 16 + ((lane >> 3) & 1) * 8 + (lane & 7);
        const uint32_t qaddr = base + (qrow * STRH + 8 * (lane >> 4)) * 2;
#pragma unroll
        for (int kb = 0; kb < 4; kb++)
            ldsm_x4(qf[kb][0], qf[kb][1], qf[kb][2], qf[kb][3],
                    qaddr + 32 * kb);
    }
    __syncthreads();   // qf read complete before producer overwrites buf0

    if (warp >= 8) {
        // ================= PRODUCER (4 warps, 128 threads) ===================
        const int ltid = tid - NCON;
        const int tx = ltid & 15, ty = ltid >> 4;      // 16 x 8
        const int grp = (lane >> 4);                    // 16-lane half
        float* sB = sm + SB_W;
        for (int rd = 0; rd < nrounds; rd++) {
            const int p = rd & 1;
            const int k0r = rd * BK2;
            if (rd >= 2) bar_sync(3 + p);               // wait buffer empty
            uint32_t* dK = sH2 + p * BUFW;
            uint32_t* dV = dK + VOFF_W;
#pragma unroll 4
            for (int i = 0; i < 16; i++) {
                const int r = ty + 8 * i;               // 0..127
                float4 kv = *(const float4*)(Kg + (size_t)(k0r + r) * kD + 4 * tx);
                const float asum = fabsf(kv.x) + fabsf(kv.y) +
                                   fabsf(kv.z) + fabsf(kv.w);
                const uint32_t bal = __ballot_sync(0xffffffffu, asum != 0.f);
                if (tx == 0)
                    sB[p * BK2 + r] =
                        (((bal >> (16 * grp)) & 0xFFFFu) == 0u) ? kPad : 0.f;
                dK[r * (STRH / 2) + 2 * tx + 0] = f2h2(kv.x, kv.y);
                dK[r * (STRH / 2) + 2 * tx + 1] = f2h2(kv.z, kv.w);
                float4 vv = *(const float4*)(Vg + (size_t)(k0r + r) * kD + 4 * tx);
                dV[r * (STRH / 2) + 2 * tx + 0] = f2h2(vv.x, vv.y);
                dV[r * (STRH / 2) + 2 * tx + 1] = f2h2(vv.z, vv.w);
            }
            bar_arrive(1 + p);                          // signal buffer full
        }
        return;
    }

    // ================== CONSUMER (8 warps, 256 threads) ======================
    const int g = lane >> 2;
    const int tig = lane & 3;
    float m0 = kPad, m1 = kPad, l0 = 0.f, l1 = 0.f;
    float o[8][4];
#pragma unroll
    for (int nb = 0; nb < 8; nb++)
#pragma unroll
        for (int j = 0; j < 4; j++) o[nb][j] = 0.f;

    const int rowg0 = q0 + warp * 16 + g;
    const int rowg1 = rowg0 + 8;
    const uint32_t lrow = lane & 15, lhi = lane >> 4;
    const uint32_t krow_in16 = 8 * (lane >> 4) + (lane & 7);
    const uint32_t kdim8 = 8 * ((lane >> 3) & 1);
    const float* sB = sm + SB_W;

    for (int rd = 0; rd < nrounds; rd++) {
        const int p = rd & 1;
        const int k0r = rd * BK2;
        bar_sync(1 + p);                                // wait buffer full
        const uint32_t kbase = base + p * BUFW * 4;
        const uint32_t vbase = kbase + VOFF_W * 4;
        const float* sBp = sB + p * BK2;

#pragma unroll
        for (int c = 0; c < 2; c++) {
            const int k0 = k0r + 64 * c;
            const bool active = (k0 <= q0 + warp * 16 + 15);
            if (active) {
                const int rb = 64 * c;

                // S = Q K^T
                float s[8][4];
#pragma unroll
                for (int nb = 0; nb < 8; nb++)
#pragma unroll
                    for (int j = 0; j < 4; j++) s[nb][j] = 0.f;
#pragma unroll
                for (int kb = 0; kb < 4; kb++) {
#pragma unroll
                    for (int nbp = 0; nbp < 4; nbp++) {
                        const uint32_t kaddr =
                            kbase + ((rb + 16 * nbp + krow_in16) * STRH +
                                     16 * kb + kdim8) * 2;
                        uint32_t b0, b1, b2, b3;
                        ldsm_x4(b0, b1, b2, b3, kaddr);
                        mma_f16(s[2 * nbp], qf[kb][0], qf[kb][1], qf[kb][2],
                                qf[kb][3], b0, b1);
                        mma_f16(s[2 * nbp + 1], qf[kb][0], qf[kb][1], qf[kb][2],
                                qf[kb][3], b2, b3);
                    }
                }

                // masks: additive pad bias + predicated causal
                const bool needC = (k0 + 63 > q0 + warp * 16);
#pragma unroll
                for (int nb = 0; nb < 8; nb++) {
                    const int cg = k0 + nb * 8 + 2 * tig;
                    const float b0 = sBp[rb + nb * 8 + 2 * tig];
                    const float b1 = sBp[rb + nb * 8 + 2 * tig + 1];
                    s[nb][0] += b0; s[nb][2] += b0;
                    s[nb][1] += b1; s[nb][3] += b1;
                    if (needC) {
                        if (cg > rowg0)     s[nb][0] = kPad;
                        if (cg + 1 > rowg0) s[nb][1] = kPad;
                        if (cg > rowg1)     s[nb][2] = kPad;
                        if (cg + 1 > rowg1) s[nb][3] = kPad;
                    }
                }

                // online softmax (base 2)
                float rmax0 = kPad, rmax1 = kPad;
#pragma unroll
                for (int nb = 0; nb < 8; nb++) {
                    rmax0 = fmaxf(rmax0, fmaxf(s[nb][0], s[nb][1]));
                    rmax1 = fmaxf(rmax1, fmaxf(s[nb][2], s[nb][3]));
                }
                rmax0 = fmaxf(rmax0, __shfl_xor_sync(0xffffffffu, rmax0, 1));
                rmax0 = fmaxf(rmax0, __shfl_xor_sync(0xffffffffu, rmax0, 2));
                rmax1 = fmaxf(rmax1, __shfl_xor_sync(0xffffffffu, rmax1, 1));
                rmax1 = fmaxf(rmax1, __shfl_xor_sync(0xffffffffu, rmax1, 2));
                const float mn0 = fmaxf(m0, rmax0);
                const float mn1 = fmaxf(m1, rmax1);
                const float corr0 = ex2f(m0 - mn0);
                const float corr1 = ex2f(m1 - mn1);
                float rs0 = 0.f, rs1 = 0.f;
#pragma unroll
                for (int nb = 0; nb < 8; nb++) {
                    s[nb][0] = ex2f(s[nb][0] - mn0);
                    s[nb][1] = ex2f(s[nb][1] - mn0);
                    s[nb][2] = ex2f(s[nb][2] - mn1);
                    s[nb][3] = ex2f(s[nb][3] - mn1);
                    rs0 += s[nb][0] + s[nb][1];
                    rs1 += s[nb][2] + s[nb][3];
                }
                rs0 += __shfl_xor_sync(0xffffffffu, rs0, 1);
                rs0 += __shfl_xor_sync(0xffffffffu, rs0, 2);
                rs1 += __shfl_xor_sync(0xffffffffu, rs1, 1);
                rs1 += __shfl_xor_sync(0xffffffffu, rs1, 2);
                l0 = l0 * corr0 + rs0; m0 = mn0;
                l1 = l1 * corr1 + rs1; m1 = mn1;
#pragma unroll
                for (int nb = 0; nb < 8; nb++) {
                    o[nb][0] *= corr0; o[nb][1] *= corr0;
                    o[nb][2] *= corr1; o[nb][3] *= corr1;
                }

                // O += P V
#pragma unroll
                for (int t = 0; t < 4; t++) {
                    const uint32_t a0 = f2h2(s[2 * t][0], s[2 * t][1]);
                    const uint32_t a1 = f2h2(s[2 * t][2], s[2 * t][3]);
                    const uint32_t a2 = f2h2(s[2 * t + 1][0], s[2 * t + 1][1]);
                    const uint32_t a3 = f2h2(s[2 * t + 1][2], s[2 * t + 1][3]);
                    const uint32_t addr0 =
                        vbase + ((64 * c + 16 * t + lrow) * STRH + 8 * lhi) * 2;
#pragma unroll
                    for (int nbp = 0; nbp < 4; nbp++) {
                        uint32_t b0, b1, b2, b3;
                        ldsm_x4_trans(b0, b1, b2, b3, addr0 + nbp * 32);
                        mma_f16(o[2 * nbp], a0, a1, a2, a3, b0, b1);
                        mma_f16(o[2 * nbp + 1], a0, a1, a2, a3, b2, b3);
                    }
                }
            }
        }
        bar_arrive(3 + p);                              // signal buffer empty
    }

    // ---- finalize -----------------------------------------------------------
    const float inv0 = 1.f / l0;
    const float inv1 = 1.f / l1;
    float* Og = O + (size_t)bn * kT * kD;
#pragma unroll
    for (int nb = 0; nb < 8; nb++) {
        *(float2*)(Og + (size_t)rowg0 * kD + nb * 8 + 2 * tig) =
            make_float2(o[nb][0] * inv0, o[nb][1] * inv0);
        *(float2*)(Og + (size_t)rowg1 * kD + nb * 8 + 2 * tig) =
            make_float2(o[nb][2] * inv1, o[nb][3] * inv1);
    }
}

extern "C" void kernel_launch(void* const* d_in, const int* in_sizes, int n_in,
                              void* d_out, int out_size) {
    const float* q = (const float*)d_in[0];
    const float* k = (const float*)d_in[1];
    const float* v = (const float*)d_in[2];
    float* o = (float*)d_out;

    const size_t smem_bytes = (size_t)SMEM_WORDS * sizeof(float);  // 73 KB
    cudaFuncSetAttribute(attn_ws_kernel,
                         cudaFuncAttributeMaxDynamicSharedMemorySize,
                         (int)smem_bytes);

    dim3 grid(kT / BM, 64);   // 8 x 64 = 512 blocks
    attn_ws_kernel<<<grid, THREADS, smem_bytes>>>(q, k, v, o);
}

// round 12
// speedup vs baseline: 1.1129x; 1.1129x over previous
#include <cuda_runtime.h>
#include <cuda_fp16.h>
#include <math.h>
#include <stdint.h>

// ----------------------------------------------------------------------------
// Causal masked softmax attention. N=64, T=1024, D=64.
// BM=64 queries/block, 4 warps, 128 threads -> 4 independent blocks/SM
// (R11 lesson: resident-block overlap beats warp specialization here).
// K/V loaded in 128-key rounds (one barrier pair per round), computed as two
// 64-key chunks. All-fp16 tensor GEMMs, fp32 accumulators, fp32 softmax.
//   QK^T: m16n8k16, A=Q regs (ldmatrix.x4 once), B=K via ldmatrix.x4.
//   PV:   m16n8k16, A=P regs (C-layout == A-layout), B=V via ldmatrix.x4.trans.
// Key-padding mask as additive bias (0/-1e30) computed at load from raw K.
// ----------------------------------------------------------------------------

namespace {
constexpr int kT = 1024;
constexpr int BM = 64;       // queries per block
constexpr int BK2 = 128;     // keys per load round (2 x 64-key compute chunks)
constexpr int kD = 64;
constexpr int THREADS = 128; // 4 warps
constexpr int STRH = 72;     // row stride in halves (144 B; ldmatrix conflict-free)
constexpr float kQScale = 0.18033688011112042f;  // (1/8) * log2(e)
constexpr float kPad = -1e30f;                   // exp2 -> exactly 0
constexpr int VOFF_H = BK2 * STRH;               // 9216 halves: V region start
constexpr int SB_W = VOFF_H;                     // word 9216: bias array
constexpr int SMEM_WORDS = SB_W + BK2;           // 9344 words = 36.5 KB
}  // namespace

__device__ __forceinline__ float ex2f(float x) {
    float r; asm("ex2.approx.ftz.f32 %0, %1;" : "=f"(r) : "f"(x)); return r;
}
__device__ __forceinline__ uint32_t f2h2(float lo, float hi) {
    __half2 h = __floats2half2_rn(lo, hi);
    return *reinterpret_cast<uint32_t*>(&h);
}
__device__ __forceinline__ void mma_f16(float (&d)[4],
                                        uint32_t a0, uint32_t a1,
                                        uint32_t a2, uint32_t a3,
                                        uint32_t b0, uint32_t b1) {
    asm volatile(
        "mma.sync.aligned.m16n8k16.row.col.f32.f16.f16.f32 "
        "{%0,%1,%2,%3}, {%4,%5,%6,%7}, {%8,%9}, {%0,%1,%2,%3};\n"
        : "+f"(d[0]), "+f"(d[1]), "+f"(d[2]), "+f"(d[3])
        : "r"(a0), "r"(a1), "r"(a2), "r"(a3), "r"(b0), "r"(b1));
}
__device__ __forceinline__ void ldsm_x4(uint32_t& r0, uint32_t& r1,
                                        uint32_t& r2, uint32_t& r3,
                                        uint32_t addr) {
    asm volatile(
        "ldmatrix.sync.aligned.m8n8.x4.shared.b16 {%0,%1,%2,%3}, [%4];\n"
        : "=r"(r0), "=r"(r1), "=r"(r2), "=r"(r3) : "r"(addr));
}
__device__ __forceinline__ void ldsm_x4_trans(uint32_t& r0, uint32_t& r1,
                                              uint32_t& r2, uint32_t& r3,
                                              uint32_t addr) {
    asm volatile(
        "ldmatrix.sync.aligned.m8n8.x4.trans.shared.b16 {%0,%1,%2,%3}, [%4];\n"
        : "=r"(r0), "=r"(r1), "=r"(r2), "=r"(r3) : "r"(addr));
}

__global__ __launch_bounds__(THREADS, 4)
void attn_bm64_kernel(const float* __restrict__ Q, const float* __restrict__ K,
                      const float* __restrict__ V, float* __restrict__ O) {
    extern __shared__ float sm[];
    uint32_t* sH2 = (uint32_t*)sm;             // K/V halves region (as half2)
    float* sB = sm + SB_W;                     // [BK2] additive pad bias

    const int tid = threadIdx.x;
    const int warp = tid >> 5;   // 0..3
    const int lane = tid & 31;
    const int g = lane >> 2;
    const int tig = lane & 3;
    const int qt = (kT / BM - 1) - blockIdx.x;   // heavy q-tiles first
    const int bn = blockIdx.y;
    const int q0 = qt * BM;

    const float* Qg = Q + ((size_t)bn * kT + q0) * kD;
    const float* Kg = K + (size_t)bn * kT * kD;
    const float* Vg = V + (size_t)bn * kT * kD;

    const int tx = tid & 15, ty = tid >> 4;      // 16x8 loader layout
    const uint32_t base = (uint32_t)__cvta_generic_to_shared(sm);  // bytes
    const uint32_t vbase = base + 2 * VOFF_H;

    // ---- stage Q (scaled fp16) rows 0..63 in the K region -------------------
#pragma unroll
    for (int i = 0; i < 8; i++) {
        const int r = ty + 8 * i;                // 0..63
        float4 qv = *(const float4*)(Qg + (size_t)r * kD + 4 * tx);
        *(uint2*)(sH2 + r * (STRH / 2) + 2 * tx) =
            make_uint2(f2h2(qv.x * kQScale, qv.y * kQScale),
                       f2h2(qv.z * kQScale, qv.w * kQScale));
    }
    __syncthreads();
    // A fragments via ldmatrix.x4 (rows g/g+8, k halves per kb)
    uint32_t qf[4][4];
    {
        const uint32_t qrow = warp * 16 + ((lane >> 3) & 1) * 8 + (lane & 7);
        const uint32_t qaddr = base + (qrow * STRH + 8 * (lane >> 4)) * 2;
#pragma unroll
        for (int kb = 0; kb < 4; kb++)
            ldsm_x4(qf[kb][0], qf[kb][1], qf[kb][2], qf[kb][3],
                    qaddr + 32 * kb);
    }

    float m0 = kPad, m1 = kPad, l0 = 0.f, l1 = 0.f;
    float o[8][4];
#pragma unroll
    for (int nb = 0; nb < 8; nb++)
#pragma unroll
        for (int j = 0; j < 4; j++) o[nb][j] = 0.f;

    const int rowg0 = q0 + warp * 16 + g;
    const int rowg1 = rowg0 + 8;
    const uint32_t lrow = lane & 15, lhi = lane >> 4;
    const uint32_t krow_in16 = 8 * (lane >> 4) + (lane & 7);
    const uint32_t kdim8 = 8 * ((lane >> 3) & 1);

    const int nrounds = (qt + 2) >> 1;           // 128-key rounds (keys <= q0+63)
    for (int rd = 0; rd < nrounds; rd++) {
        const int k0r = rd * BK2;
        __syncthreads();   // prior round's ldmatrix reads done (also Q staging)

        // ---- load 128 K rows (+bias) and 128 V rows, fp16-convert -----------
#pragma unroll
        for (int i = 0; i < 16; i++) {
            const int r = ty + 8 * i;            // 0..127
            float4 kv = *(const float4*)(Kg + (size_t)(k0r + r) * kD + 4 * tx);
            float asum = fabsf(kv.x) + fabsf(kv.y) + fabsf(kv.z) + fabsf(kv.w);
#pragma unroll
            for (int off = 8; off > 0; off >>= 1)
                asum += __shfl_xor_sync(0xffffffffu, asum, off, 16);
            if (tx == 0) sB[r] = (asum == 0.f) ? kPad : 0.f;
            *(uint2*)(sH2 + r * (STRH / 2) + 2 * tx) =
                make_uint2(f2h2(kv.x, kv.y), f2h2(kv.z, kv.w));
            float4 vv = *(const float4*)(Vg + (size_t)(k0r + r) * kD + 4 * tx);
            *(uint2*)(sH2 + (VOFF_H / 2) + r * (STRH / 2) + 2 * tx) =
                make_uint2(f2h2(vv.x, vv.y), f2h2(vv.z, vv.w));
        }
        __syncthreads();

        // ---- two 64-key compute chunks from this round ----------------------
#pragma unroll
        for (int c = 0; c < 2; c++) {
            const int k0 = k0r + 64 * c;
            if (k0 > q0 + warp * 16 + 15) continue;   // no barriers inside
            const int rb = 64 * c;                    // smem row base

            // S = Q K^T
            float s[8][4];
#pragma unroll
            for (int nb = 0; nb < 8; nb++)
#pragma unroll
                for (int j = 0; j < 4; j++) s[nb][j] = 0.f;
#pragma unroll
            for (int kb = 0; kb < 4; kb++) {
#pragma unroll
                for (int nbp = 0; nbp < 4; nbp++) {
                    const uint32_t kaddr =
                        base + ((rb + 16 * nbp + krow_in16) * STRH +
                                16 * kb + kdim8) * 2;
                    uint32_t b0, b1, b2, b3;
                    ldsm_x4(b0, b1, b2, b3, kaddr);
                    mma_f16(s[2 * nbp], qf[kb][0], qf[kb][1], qf[kb][2],
                            qf[kb][3], b0, b1);
                    mma_f16(s[2 * nbp + 1], qf[kb][0], qf[kb][1], qf[kb][2],
                            qf[kb][3], b2, b3);
                }
            }

            // masks: additive pad bias + predicated causal
            const bool needC = (k0 + 63 > q0 + warp * 16);
#pragma unroll
            for (int nb = 0; nb < 8; nb++) {
                const int cg = k0 + nb * 8 + 2 * tig;
                const float b0 = sB[rb + nb * 8 + 2 * tig];
                const float b1 = sB[rb + nb * 8 + 2 * tig + 1];
                s[nb][0] += b0; s[nb][2] += b0;
                s[nb][1] += b1; s[nb][3] += b1;
                if (needC) {
                    if (cg > rowg0)     s[nb][0] = kPad;
                    if (cg + 1 > rowg0) s[nb][1] = kPad;
                    if (cg > rowg1)     s[nb][2] = kPad;
                    if (cg + 1 > rowg1) s[nb][3] = kPad;
                }
            }

            // online softmax (base 2), P in registers
            float rmax0 = kPad, rmax1 = kPad;
#pragma unroll
            for (int nb = 0; nb < 8; nb++) {
                rmax0 = fmaxf(rmax0, fmaxf(s[nb][0], s[nb][1]));
                rmax1 = fmaxf(rmax1, fmaxf(s[nb][2], s[nb][3]));
            }
            rmax0 = fmaxf(rmax0, __shfl_xor_sync(0xffffffffu, rmax0, 1));
            rmax0 = fmaxf(rmax0, __shfl_xor_sync(0xffffffffu, rmax0, 2));
            rmax1 = fmaxf(rmax1, __shfl_xor_sync(0xffffffffu, rmax1, 1));
            rmax1 = fmaxf(rmax1, __shfl_xor_sync(0xffffffffu, rmax1, 2));
            const float mn0 = fmaxf(m0, rmax0);
            const float mn1 = fmaxf(m1, rmax1);
            const float corr0 = ex2f(m0 - mn0);
            const float corr1 = ex2f(m1 - mn1);
            float rs0 = 0.f, rs1 = 0.f;
#pragma unroll
            for (int nb = 0; nb < 8; nb++) {
                s[nb][0] = ex2f(s[nb][0] - mn0);
                s[nb][1] = ex2f(s[nb][1] - mn0);
                s[nb][2] = ex2f(s[nb][2] - mn1);
                s[nb][3] = ex2f(s[nb][3] - mn1);
                rs0 += s[nb][0] + s[nb][1];
                rs1 += s[nb][2] + s[nb][3];
            }
            rs0 += __shfl_xor_sync(0xffffffffu, rs0, 1);
            rs0 += __shfl_xor_sync(0xffffffffu, rs0, 2);
            rs1 += __shfl_xor_sync(0xffffffffu, rs1, 1);
            rs1 += __shfl_xor_sync(0xffffffffu, rs1, 2);
            l0 = l0 * corr0 + rs0; m0 = mn0;
            l1 = l1 * corr1 + rs1; m1 = mn1;
#pragma unroll
            for (int nb = 0; nb < 8; nb++) {
                o[nb][0] *= corr0; o[nb][1] *= corr0;
                o[nb][2] *= corr1; o[nb][3] *= corr1;
            }

            // O += P V (B via ldmatrix.x4.trans)
#pragma unroll
            for (int t = 0; t < 4; t++) {
                const uint32_t a0 = f2h2(s[2 * t][0], s[2 * t][1]);
                const uint32_t a1 = f2h2(s[2 * t][2], s[2 * t][3]);
                const uint32_t a2 = f2h2(s[2 * t + 1][0], s[2 * t + 1][1]);
                const uint32_t a3 = f2h2(s[2 * t + 1][2], s[2 * t + 1][3]);
                const uint32_t addr0 =
                    vbase + ((rb + 16 * t + lrow) * STRH + 8 * lhi) * 2;
#pragma unroll
                for (int nbp = 0; nbp < 4; nbp++) {
                    uint32_t b0, b1, b2, b3;
                    ldsm_x4_trans(b0, b1, b2, b3, addr0 + nbp * 32);
                    mma_f16(o[2 * nbp], a0, a1, a2, a3, b0, b1);
                    mma_f16(o[2 * nbp + 1], a0, a1, a2, a3, b2, b3);
                }
            }
        }
    }

    // ---- finalize -----------------------------------------------------------
    const float inv0 = 1.f / l0;
    const float inv1 = 1.f / l1;
    float* Og = O + (size_t)bn * kT * kD;
#pragma unroll
    for (int nb = 0; nb < 8; nb++) {
        *(float2*)(Og + (size_t)rowg0 * kD + nb * 8 + 2 * tig) =
            make_float2(o[nb][0] * inv0, o[nb][1] * inv0);
        *(float2*)(Og + (size_t)rowg1 * kD + nb * 8 + 2 * tig) =
            make_float2(o[nb][2] * inv1, o[nb][3] * inv1);
    }
}

extern "C" void kernel_launch(void* const* d_in, const int* in_sizes, int n_in,
                              void* d_out, int out_size) {
    const float* q = (const float*)d_in[0];
    const float* k = (const float*)d_in[1];
    const float* v = (const float*)d_in[2];
    float* o = (float*)d_out;

    const size_t smem_bytes = (size_t)SMEM_WORDS * sizeof(float);  // 36.5 KB
    cudaFuncSetAttribute(attn_bm64_kernel,
                         cudaFuncAttributeMaxDynamicSharedMemorySize,
                         (int)smem_bytes);

    dim3 grid(kT / BM, 64);   // 16 x 64 = 1024 blocks
    attn_bm64_kernel<<<grid, THREADS, smem_bytes>>>(q, k, v, o);
}

// round 13
// speedup vs baseline: 1.2317x; 1.1068x over previous
#include <cuda_runtime.h>
#include <cuda_fp16.h>
#include <math.h>
#include <stdint.h>

// ----------------------------------------------------------------------------
// Causal masked softmax attention. N=64, T=1024, D=64.
// BM=128 queries/block (8 warps), K/V loaded in 256-key rounds (one barrier
// pair per round), computed as four 64-key chunks. All-fp16 tensor GEMMs,
// fp32 accumulators, fp32 softmax.
//   QK^T: m16n8k16, A=Q regs (ldmatrix.x4 once), B=K via ldmatrix.x4.
//   PV:   m16n8k16, A=P regs (C-layout == A-layout), B=V via ldmatrix.x4.trans.
// Key-padding mask: additive bias (0/-1e30) via one ballot per loader step.
// (R12 lesson: BM=128 loader amortization > resident-block count; R10 base.)
// ----------------------------------------------------------------------------

namespace {
constexpr int kT = 1024;
constexpr int BM = 128;
constexpr int BK2 = 256;     // keys per load round (4 x 64-key compute chunks)
constexpr int kD = 64;
constexpr int THREADS = 256;
constexpr int STRH = 72;     // row stride in halves (144 B; ldmatrix conflict-free)
constexpr float kQScale = 0.18033688011112042f;  // (1/8) * log2(e)
constexpr float kPad = -1e30f;                   // exp2 -> exactly 0
constexpr int VOFF_H = BK2 * STRH;               // 18432 halves: V region start
constexpr int SB_W = BK2 * (STRH / 2) * 2;       // word 18432: bias array
constexpr int SMEM_WORDS = SB_W + BK2;           // 18688 words = 73 KB
}  // namespace

__device__ __forceinline__ float ex2f(float x) {
    float r; asm("ex2.approx.ftz.f32 %0, %1;" : "=f"(r) : "f"(x)); return r;
}
__device__ __forceinline__ uint32_t f2h2(float lo, float hi) {
    __half2 h = __floats2half2_rn(lo, hi);
    return *reinterpret_cast<uint32_t*>(&h);
}
__device__ __forceinline__ void mma_f16(float (&d)[4],
                                        uint32_t a0, uint32_t a1,
                                        uint32_t a2, uint32_t a3,
                                        uint32_t b0, uint32_t b1) {
    asm volatile(
        "mma.sync.aligned.m16n8k16.row.col.f32.f16.f16.f32 "
        "{%0,%1,%2,%3}, {%4,%5,%6,%7}, {%8,%9}, {%0,%1,%2,%3};\n"
        : "+f"(d[0]), "+f"(d[1]), "+f"(d[2]), "+f"(d[3])
        : "r"(a0), "r"(a1), "r"(a2), "r"(a3), "r"(b0), "r"(b1));
}
__device__ __forceinline__ void ldsm_x4(uint32_t& r0, uint32_t& r1,
                                        uint32_t& r2, uint32_t& r3,
                                        uint32_t addr) {
    asm volatile(
        "ldmatrix.sync.aligned.m8n8.x4.shared.b16 {%0,%1,%2,%3}, [%4];\n"
        : "=r"(r0), "=r"(r1), "=r"(r2), "=r"(r3) : "r"(addr));
}
__device__ __forceinline__ void ldsm_x4_trans(uint32_t& r0, uint32_t& r1,
                                              uint32_t& r2, uint32_t& r3,
                                              uint32_t addr) {
    asm volatile(
        "ldmatrix.sync.aligned.m8n8.x4.trans.shared.b16 {%0,%1,%2,%3}, [%4];\n"
        : "=r"(r0), "=r"(r1), "=r"(r2), "=r"(r3) : "r"(addr));
}

__global__ __launch_bounds__(THREADS, 2)
void attn_r4_kernel(const float* __restrict__ Q, const float* __restrict__ K,
                    const float* __restrict__ V, float* __restrict__ O) {
    extern __shared__ float sm[];
    uint32_t* sH2 = (uint32_t*)sm;             // K/V halves region (as half2)
    float* sB = sm + SB_W;                     // [BK2] additive pad bias

    const int tid = threadIdx.x;
    const int warp = tid >> 5;   // 0..7
    const int lane = tid & 31;
    const int g = lane >> 2;
    const int tig = lane & 3;
    const int qt = (kT / BM - 1) - blockIdx.x;   // heavy q-tiles first
    const int bn = blockIdx.y;
    const int q0 = qt * BM;

    const float* Qg = Q + ((size_t)bn * kT + q0) * kD;
    const float* Kg = K + (size_t)bn * kT * kD;
    const float* Vg = V + (size_t)bn * kT * kD;

    const int tx = tid & 15, ty = tid >> 4;      // 16x16 loader layout
    const uint32_t base = (uint32_t)__cvta_generic_to_shared(sm);  // bytes
    const uint32_t vbase = base + 2 * VOFF_H;
    const int bgrp = lane >> 4;                  // 16-lane ballot slice

    // ---- stage Q (scaled fp16) rows 0..127 in the K region ------------------
#pragma unroll
    for (int i = 0; i < 8; i++) {
        const int r = ty + 16 * i;               // 0..127
        float4 qv = *(const float4*)(Qg + (size_t)r * kD + 4 * tx);
        *(uint2*)(sH2 + r * (STRH / 2) + 2 * tx) =
            make_uint2(f2h2(qv.x * kQScale, qv.y * kQScale),
                       f2h2(qv.z * kQScale, qv.w * kQScale));
    }
    __syncthreads();
    // A fragments via ldmatrix.x4 (rows g/g+8, k halves per kb)
    uint32_t qf[4][4];
    {
        const uint32_t qrow = warp * 16 + ((lane >> 3) & 1) * 8 + (lane & 7);
        const uint32_t qaddr = base + (qrow * STRH + 8 * (lane >> 4)) * 2;
#pragma unroll
        for (int kb = 0; kb < 4; kb++)
            ldsm_x4(qf[kb][0], qf[kb][1], qf[kb][2], qf[kb][3],
                    qaddr + 32 * kb);
    }

    float m0 = kPad, m1 = kPad, l0 = 0.f, l1 = 0.f;
    float o[8][4];
#pragma unroll
    for (int nb = 0; nb < 8; nb++)
#pragma unroll
        for (int j = 0; j < 4; j++) o[nb][j] = 0.f;

    const int rowg0 = q0 + warp * 16 + g;
    const int rowg1 = rowg0 + 8;
    const uint32_t lrow = lane & 15, lhi = lane >> 4;
    const uint32_t krow_in16 = 8 * (lane >> 4) + (lane & 7);
    const uint32_t kdim8 = 8 * ((lane >> 3) & 1);

    const int nrounds = (qt + 2) >> 1;           // 256-key rounds
    for (int rd = 0; rd < nrounds; rd++) {
        const int k0r = rd * BK2;
        __syncthreads();   // prior round's ldmatrix reads done (also Q staging)

        // ---- load 256 K rows (+ballot bias) and 256 V rows, fp16-convert ----
#pragma unroll
        for (int i = 0; i < 16; i++) {
            const int r = ty + 16 * i;           // 0..255
            float4 kv = *(const float4*)(Kg + (size_t)(k0r + r) * kD + 4 * tx);
            const float asum = fabsf(kv.x) + fabsf(kv.y) +
                               fabsf(kv.z) + fabsf(kv.w);
            const uint32_t bal = __ballot_sync(0xffffffffu, asum != 0.f);
            if (tx == 0)
                sB[r] = (((bal >> (16 * bgrp)) & 0xFFFFu) == 0u) ? kPad : 0.f;
            *(uint2*)(sH2 + r * (STRH / 2) + 2 * tx) =
                make_uint2(f2h2(kv.x, kv.y), f2h2(kv.z, kv.w));
            float4 vv = *(const float4*)(Vg + (size_t)(k0r + r) * kD + 4 * tx);
            *(uint2*)(sH2 + (VOFF_H / 2) + r * (STRH / 2) + 2 * tx) =
                make_uint2(f2h2(vv.x, vv.y), f2h2(vv.z, vv.w));
        }
        __syncthreads();

        // ---- four 64-key compute chunks from this round ---------------------
#pragma unroll
        for (int c = 0; c < 4; c++) {
            const int k0 = k0r + 64 * c;
            if (k0 > q0 + warp * 16 + 15) continue;   // no barriers inside
            const int rb = 64 * c;                    // smem row base

            // S = Q K^T
            float s[8][4];
#pragma unroll
            for (int nb = 0; nb < 8; nb++)
#pragma unroll
                for (int j = 0; j < 4; j++) s[nb][j] = 0.f;
#pragma unroll
            for (int kb = 0; kb < 4; kb++) {
#pragma unroll
                for (int nbp = 0; nbp < 4; nbp++) {
                    const uint32_t kaddr =
                        base + ((rb + 16 * nbp + krow_in16) * STRH +
                                16 * kb + kdim8) * 2;
                    uint32_t b0, b1, b2, b3;
                    ldsm_x4(b0, b1, b2, b3, kaddr);
                    mma_f16(s[2 * nbp], qf[kb][0], qf[kb][1], qf[kb][2],
                            qf[kb][3], b0, b1);
                    mma_f16(s[2 * nbp + 1], qf[kb][0], qf[kb][1], qf[kb][2],
                            qf[kb][3], b2, b3);
                }
            }

            // masks: additive pad bias + predicated causal
            const bool needC = (k0 + 63 > q0 + warp * 16);
#pragma unroll
            for (int nb = 0; nb < 8; nb++) {
                const int cg = k0 + nb * 8 + 2 * tig;
                const float b0 = sB[rb + nb * 8 + 2 * tig];
                const float b1 = sB[rb + nb * 8 + 2 * tig + 1];
                s[nb][0] += b0; s[nb][2] += b0;
                s[nb][1] += b1; s[nb][3] += b1;
                if (needC) {
                    if (cg > rowg0)     s[nb][0] = kPad;
                    if (cg + 1 > rowg0) s[nb][1] = kPad;
                    if (cg > rowg1)     s[nb][2] = kPad;
                    if (cg + 1 > rowg1) s[nb][3] = kPad;
                }
            }

            // online softmax (base 2), P in registers
            float rmax0 = kPad, rmax1 = kPad;
#pragma unroll
            for (int nb = 0; nb < 8; nb++) {
                rmax0 = fmaxf(rmax0, fmaxf(s[nb][0], s[nb][1]));
                rmax1 = fmaxf(rmax1, fmaxf(s[nb][2], s[nb][3]));
            }
            rmax0 = fmaxf(rmax0, __shfl_xor_sync(0xffffffffu, rmax0, 1));
            rmax0 = fmaxf(rmax0, __shfl_xor_sync(0xffffffffu, rmax0, 2));
            rmax1 = fmaxf(rmax1, __shfl_xor_sync(0xffffffffu, rmax1, 1));
            rmax1 = fmaxf(rmax1, __shfl_xor_sync(0xffffffffu, rmax1, 2));
            const float mn0 = fmaxf(m0, rmax0);
            const float mn1 = fmaxf(m1, rmax1);
            const float corr0 = ex2f(m0 - mn0);
            const float corr1 = ex2f(m1 - mn1);
            float rs0 = 0.f, rs1 = 0.f;
#pragma unroll
            for (int nb = 0; nb < 8; nb++) {
                s[nb][0] = ex2f(s[nb][0] - mn0);
                s[nb][1] = ex2f(s[nb][1] - mn0);
                s[nb][2] = ex2f(s[nb][2] - mn1);
                s[nb][3] = ex2f(s[nb][3] - mn1);
                rs0 += s[nb][0] + s[nb][1];
                rs1 += s[nb][2] + s[nb][3];
            }
            rs0 += __shfl_xor_sync(0xffffffffu, rs0, 1);
            rs0 += __shfl_xor_sync(0xffffffffu, rs0, 2);
            rs1 += __shfl_xor_sync(0xffffffffu, rs1, 1);
            rs1 += __shfl_xor_sync(0xffffffffu, rs1, 2);
            l0 = l0 * corr0 + rs0; m0 = mn0;
            l1 = l1 * corr1 + rs1; m1 = mn1;
#pragma unroll
            for (int nb = 0; nb < 8; nb++) {
                o[nb][0] *= corr0; o[nb][1] *= corr0;
                o[nb][2] *= corr1; o[nb][3] *= corr1;
            }

            // O += P V (B via ldmatrix.x4.trans)
#pragma unroll
            for (int t = 0; t < 4; t++) {
                const uint32_t a0 = f2h2(s[2 * t][0], s[2 * t][1]);
                const uint32_t a1 = f2h2(s[2 * t][2], s[2 * t][3]);
                const uint32_t a2 = f2h2(s[2 * t + 1][0], s[2 * t + 1][1]);
                const uint32_t a3 = f2h2(s[2 * t + 1][2], s[2 * t + 1][3]);
                const uint32_t addr0 =
                    vbase + ((rb + 16 * t + lrow) * STRH + 8 * lhi) * 2;
#pragma unroll
                for (int nbp = 0; nbp < 4; nbp++) {
                    uint32_t b0, b1, b2, b3;
                    ldsm_x4_trans(b0, b1, b2, b3, addr0 + nbp * 32);
                    mma_f16(o[2 * nbp], a0, a1, a2, a3, b0, b1);
                    mma_f16(o[2 * nbp + 1], a0, a1, a2, a3, b2, b3);
                }
            }
        }
    }

    // ---- finalize -----------------------------------------------------------
    const float inv0 = 1.f / l0;
    const float inv1 = 1.f / l1;
    float* Og = O + (size_t)bn * kT * kD;
#pragma unroll
    for (int nb = 0; nb < 8; nb++) {
        *(float2*)(Og + (size_t)rowg0 * kD + nb * 8 + 2 * tig) =
            make_float2(o[nb][0] * inv0, o[nb][1] * inv0);
        *(float2*)(Og + (size_t)rowg1 * kD + nb * 8 + 2 * tig) =
            make_float2(o[nb][2] * inv1, o[nb][3] * inv1);
    }
}

extern "C" void kernel_launch(void* const* d_in, const int* in_sizes, int n_in,
                              void* d_out, int out_size) {
    const float* q = (const float*)d_in[0];
    const float* k = (const float*)d_in[1];
    const float* v = (const float*)d_in[2];
    float* o = (float*)d_out;

    const size_t smem_bytes = (size_t)SMEM_WORDS * sizeof(float);  // 73 KB
    cudaFuncSetAttribute(attn_r4_kernel,
                         cudaFuncAttributeMaxDynamicSharedMemorySize,
                         (int)smem_bytes);

    dim3 grid(kT / BM, 64);   // 8 x 64 = 512 blocks
    attn_r4_kernel<<<grid, THREADS, smem_bytes>>>(q, k, v, o);
}